// round 13
// baseline (speedup 1.0000x reference)
#include <cuda_runtime.h>
#include <math.h>

#define BB   4
#define CH   32
#define GCH  384
#define HH   224
#define WW   224
#define HW   50176
#define NPLANE 6422528        // 4*32*224*224
#define N4     1605632        // NPLANE/4
#define WT   8                // scan tile width (steps per SMEM tile)
#define SSTR 233              // padded SMEM row stride

// Scratch (static device globals)
__device__ __align__(16) float g_y32[NPLANE];        // conv1 output
__device__ __align__(16) float g_dirA[4 * NPLANE];   // pass-1 directional outputs
__device__ __align__(16) float g_dirB[4 * NPLANE];   // pass-2 directional outputs
__device__ __align__(16) float g_s2[NPLANE];         // max of pass-2

// ---------------------------------------------------------------------------
// conv1: y [4,2,224,224] -> g_y32 [4,32,224,224], 3x3 same
// ---------------------------------------------------------------------------
__global__ void __launch_bounds__(224) conv1_kernel(
    const float* __restrict__ y, const float* __restrict__ w3)
{
    int b = blockIdx.x / HH;
    int h = blockIdx.x % HH;
    int tid = threadIdx.x;

    __shared__ float si[2][3][WW + 2];
    __shared__ float sw[32 * 2 * 9];

    for (int i = tid; i < 576; i += 224) sw[i] = w3[i];

    #pragma unroll
    for (int ic = 0; ic < 2; ic++)
        #pragma unroll
        for (int r = 0; r < 3; r++) {
            int hh = h + r - 1;
            float v = (hh >= 0 && hh < HH)
                        ? y[((size_t)(b * 2 + ic) * HH + hh) * WW + tid] : 0.f;
            si[ic][r][tid + 1] = v;
            if (tid < 2) si[ic][r][tid * (WW + 1)] = 0.f;
        }
    __syncthreads();

    float v[18];
    #pragma unroll
    for (int ic = 0; ic < 2; ic++)
        #pragma unroll
        for (int r = 0; r < 3; r++)
            #pragma unroll
            for (int dx = 0; dx < 3; dx++)
                v[ic * 9 + r * 3 + dx] = si[ic][r][tid + dx];

    for (int oc = 0; oc < 32; oc++) {
        float acc = 0.f;
        #pragma unroll
        for (int k = 0; k < 18; k++) acc = fmaf(v[k], sw[oc * 18 + k], acc);
        g_y32[((size_t)(b * 32 + oc) * HH + h) * WW + tid] = acc;
    }
}

// ---------------------------------------------------------------------------
// Propagation pass 1 (R1-exact): one CTA per (dir, b, c) plane, 224 threads.
// x = g_y32. Output -> g_dirA.
// dir map: 0=lr(hor,fwd) 1=rl(vert,rev) 2=du(vert,fwd) 3=ud(hor,rev)
// ---------------------------------------------------------------------------
__global__ void __launch_bounds__(224) prop1_kernel(
    const float* __restrict__ gates)
{
    int pid = blockIdx.x;           // 0..511
    int d  = pid >> 7;
    int bc = pid & 127;
    int b  = bc >> 5;
    int c  = bc & 31;
    bool hor = (d == 0 || d == 3);
    bool rev = (d == 1 || d == 3);

    const float* xp  = g_y32 + (size_t)bc * HW;
    float*       op  = g_dirA + (size_t)(d * 128 + bc) * HW;
    const float* g1p = gates + ((size_t)b * GCH + d * 96 + c) * HW;
    const float* g2p = g1p + (size_t)32 * HW;
    const float* g3p = g1p + (size_t)64 * HW;

    __shared__ float tx[WT * SSTR], t1[WT * SSTR], t2[WT * SSTR],
                     t3[WT * SSTR], to[WT * SSTR];
    __shared__ float hb[2][WW + 2];

    int tid = threadIdx.x;
    for (int i = tid; i < 2 * (WW + 2); i += 224) ((float*)hb)[i] = 0.f;

    float hreg = 0.f;

    for (int tb = 0; tb < HH / WT; tb++) {
        int t0 = tb * WT;

        if (hor) {
            #pragma unroll
            for (int i = 0; i < WT; i++) {
                int idx = i * 224 + tid;
                int s = idx >> 3, j = idx & 7;
                int tg = rev ? (223 - t0 - j) : (t0 + j);
                int off = s * WW + tg;
                int m = j * SSTR + s;
                tx[m] = xp[off];  t1[m] = g1p[off];
                t2[m] = g2p[off]; t3[m] = g3p[off];
            }
        } else {
            #pragma unroll
            for (int i = 0; i < WT; i++) {
                int tg = rev ? (223 - t0 - i) : (t0 + i);
                int off = tg * WW + tid;
                int m = i * SSTR + tid;
                tx[m] = xp[off];  t1[m] = g1p[off];
                t2[m] = g2p[off]; t3[m] = g3p[off];
            }
        }
        __syncthreads();

        #pragma unroll
        for (int j = 0; j < WT; j++) {
            int t = t0 + j;
            const float* hp = hb[t & 1];
            float*       hc = hb[(t & 1) ^ 1];
            int m = j * SSTR + tid;
            float xv = tx[m], a1 = t1[m], a2 = t2[m], a3 = t3[m];
            float sa = fabsf(a1) + fabsf(a2) + fabsf(a3);
            float inv = __fdividef(1.0f, fmaxf(sa, 1.0f));
            a1 *= inv; a2 *= inv; a3 *= inv;
            float hn = (1.0f - a1 - a2 - a3) * xv
                     + a1 * hp[tid] + a2 * hreg + a3 * hp[tid + 2];
            hc[tid + 1] = hn;
            to[m] = hn;
            hreg = hn;
            __syncthreads();
        }

        if (hor) {
            #pragma unroll
            for (int i = 0; i < WT; i++) {
                int idx = i * 224 + tid;
                int s = idx >> 3, j = idx & 7;
                int tg = rev ? (223 - t0 - j) : (t0 + j);
                op[s * WW + tg] = to[j * SSTR + s];
            }
        } else {
            #pragma unroll
            for (int i = 0; i < WT; i++) {
                int tg = rev ? (223 - t0 - i) : (t0 + i);
                op[tg * WW + tid] = to[i * SSTR + tid];
            }
        }
    }
}

// ---------------------------------------------------------------------------
// Propagation pass 2: identical structure, but x = max over the 4 pass-1
// direction buffers (inline; eliminates the intermediate max kernel).
// Output -> g_dirB.
// ---------------------------------------------------------------------------
__global__ void __launch_bounds__(224) prop2_kernel(
    const float* __restrict__ gates)
{
    int pid = blockIdx.x;           // 0..511
    int d  = pid >> 7;
    int bc = pid & 127;
    int b  = bc >> 5;
    int c  = bc & 31;
    bool hor = (d == 0 || d == 3);
    bool rev = (d == 1 || d == 3);

    const float* x0  = g_dirA + (size_t)bc * HW;              // dir 0 plane
    float*       op  = g_dirB + (size_t)(d * 128 + bc) * HW;
    const float* g1p = gates + ((size_t)b * GCH + d * 96 + c) * HW;
    const float* g2p = g1p + (size_t)32 * HW;
    const float* g3p = g1p + (size_t)64 * HW;

    __shared__ float tx[WT * SSTR], t1[WT * SSTR], t2[WT * SSTR],
                     t3[WT * SSTR], to[WT * SSTR];
    __shared__ float hb[2][WW + 2];

    int tid = threadIdx.x;
    for (int i = tid; i < 2 * (WW + 2); i += 224) ((float*)hb)[i] = 0.f;

    float hreg = 0.f;

    for (int tb = 0; tb < HH / WT; tb++) {
        int t0 = tb * WT;

        if (hor) {
            #pragma unroll
            for (int i = 0; i < WT; i++) {
                int idx = i * 224 + tid;
                int s = idx >> 3, j = idx & 7;
                int tg = rev ? (223 - t0 - j) : (t0 + j);
                int off = s * WW + tg;
                int m = j * SSTR + s;
                float v0 = x0[off];
                float v1 = x0[off + 1 * (size_t)NPLANE];
                float v2 = x0[off + 2 * (size_t)NPLANE];
                float v3 = x0[off + 3 * (size_t)NPLANE];
                tx[m] = fmaxf(fmaxf(v0, v1), fmaxf(v2, v3));
                t1[m] = g1p[off];
                t2[m] = g2p[off]; t3[m] = g3p[off];
            }
        } else {
            #pragma unroll
            for (int i = 0; i < WT; i++) {
                int tg = rev ? (223 - t0 - i) : (t0 + i);
                int off = tg * WW + tid;
                int m = i * SSTR + tid;
                float v0 = x0[off];
                float v1 = x0[off + 1 * (size_t)NPLANE];
                float v2 = x0[off + 2 * (size_t)NPLANE];
                float v3 = x0[off + 3 * (size_t)NPLANE];
                tx[m] = fmaxf(fmaxf(v0, v1), fmaxf(v2, v3));
                t1[m] = g1p[off];
                t2[m] = g2p[off]; t3[m] = g3p[off];
            }
        }
        __syncthreads();

        #pragma unroll
        for (int j = 0; j < WT; j++) {
            int t = t0 + j;
            const float* hp = hb[t & 1];
            float*       hc = hb[(t & 1) ^ 1];
            int m = j * SSTR + tid;
            float xv = tx[m], a1 = t1[m], a2 = t2[m], a3 = t3[m];
            float sa = fabsf(a1) + fabsf(a2) + fabsf(a3);
            float inv = __fdividef(1.0f, fmaxf(sa, 1.0f));
            a1 *= inv; a2 *= inv; a3 *= inv;
            float hn = (1.0f - a1 - a2 - a3) * xv
                     + a1 * hp[tid] + a2 * hreg + a3 * hp[tid + 2];
            hc[tid + 1] = hn;
            to[m] = hn;
            hreg = hn;
            __syncthreads();
        }

        if (hor) {
            #pragma unroll
            for (int i = 0; i < WT; i++) {
                int idx = i * 224 + tid;
                int s = idx >> 3, j = idx & 7;
                int tg = rev ? (223 - t0 - j) : (t0 + j);
                op[s * WW + tg] = to[j * SSTR + s];
            }
        } else {
            #pragma unroll
            for (int i = 0; i < WT; i++) {
                int tg = rev ? (223 - t0 - i) : (t0 + i);
                op[tg * WW + tid] = to[i * SSTR + tid];
            }
        }
    }
}

// ---------------------------------------------------------------------------
// max over 4 pass-2 direction buffers -> g_s2
// ---------------------------------------------------------------------------
__global__ void max_kernel()
{
    int i = blockIdx.x * blockDim.x + threadIdx.x;
    if (i >= N4) return;
    const float4* d0 = (const float4*)g_dirB;
    float4 a = d0[i];
    float4 b = d0[i + N4];
    float4 c = d0[i + 2 * N4];
    float4 e = d0[i + 3 * N4];
    float4 r;
    r.x = fmaxf(fmaxf(a.x, b.x), fmaxf(c.x, e.x));
    r.y = fmaxf(fmaxf(a.y, b.y), fmaxf(c.y, e.y));
    r.z = fmaxf(fmaxf(a.z, b.z), fmaxf(c.z, e.z));
    r.w = fmaxf(fmaxf(a.w, b.w), fmaxf(c.w, e.w));
    ((float4*)g_s2)[i] = r;
}

// ---------------------------------------------------------------------------
// conv2 (32->2, 3x3 same) + log_softmax over channel dim (2)
// ---------------------------------------------------------------------------
__global__ void __launch_bounds__(224) conv2_ls_kernel(
    const float* __restrict__ w4, float* __restrict__ out)
{
    int b = blockIdx.x / HH;
    int h = blockIdx.x % HH;
    int tid = threadIdx.x;

    __shared__ float si[16][3][WW + 2];
    __shared__ float sw[2 * 32 * 9];

    for (int i = tid; i < 576; i += 224) sw[i] = w4[i];

    float acc0 = 0.f, acc1 = 0.f;

    for (int chunk = 0; chunk < 2; chunk++) {
        __syncthreads();
        for (int icl = 0; icl < 16; icl++) {
            int ic = chunk * 16 + icl;
            #pragma unroll
            for (int r = 0; r < 3; r++) {
                int hh = h + r - 1;
                float v = (hh >= 0 && hh < HH)
                    ? g_s2[((size_t)(b * 32 + ic) * HH + hh) * WW + tid] : 0.f;
                si[icl][r][tid + 1] = v;
                if (tid < 2) si[icl][r][tid * (WW + 1)] = 0.f;
            }
        }
        __syncthreads();
        for (int icl = 0; icl < 16; icl++) {
            int ic = chunk * 16 + icl;
            #pragma unroll
            for (int r = 0; r < 3; r++)
                #pragma unroll
                for (int dx = 0; dx < 3; dx++) {
                    float v = si[icl][r][tid + dx];
                    int k = ic * 9 + r * 3 + dx;
                    acc0 = fmaf(v, sw[k], acc0);
                    acc1 = fmaf(v, sw[288 + k], acc1);
                }
        }
    }

    float m  = fmaxf(acc0, acc1);
    float e0 = __expf(acc0 - m), e1 = __expf(acc1 - m);
    float lse = m + __logf(e0 + e1);
    size_t o = ((size_t)b * 2 * HH + h) * WW + tid;
    out[o]      = acc0 - lse;
    out[o + HW] = acc1 - lse;
}

// ---------------------------------------------------------------------------
extern "C" void kernel_launch(void* const* d_in, const int* in_sizes, int n_in,
                              void* d_out, int out_size)
{
    const float* gates = (const float*)d_in[0];  // [4,384,224,224]
    const float* y     = (const float*)d_in[1];  // [4,2,224,224]
    const float* w3    = (const float*)d_in[2];  // [32,2,3,3]
    const float* w4    = (const float*)d_in[3];  // [2,32,3,3]
    float* out = (float*)d_out;                  // [4,2,224,224]

    (void)in_sizes; (void)n_in; (void)out_size;

    conv1_kernel<<<BB * HH, 224>>>(y, w3);
    prop1_kernel<<<512, 224>>>(gates);       // g_y32 -> g_dirA
    prop2_kernel<<<512, 224>>>(gates);       // max(dirA) inline -> g_dirB
    max_kernel<<<(N4 + 255) / 256, 256>>>(); // g_dirB -> g_s2
    conv2_ls_kernel<<<BB * HH, 224>>>(w4, out);
}

// round 14
// speedup vs baseline: 1.2139x; 1.2139x over previous
#include <cuda_runtime.h>
#include <math.h>

#define BB   4
#define CH   32
#define GCH  384
#define HH   224
#define WW   224
#define HW   50176
#define NPLANE 6422528        // 4*32*224*224
#define N4     1605632        // NPLANE/4
#define WT   8                // scan tile width (steps per SMEM tile)
#define NSTR 36               // nrm row stride in floats (per element: 8 steps x4)
#define OSTR 233              // to-buffer stride

// Scratch (static device globals)
__device__ __align__(16) float g_y32[NPLANE];        // conv1 output
__device__ __align__(16) float g_dir[4 * NPLANE];    // directional outputs
__device__ __align__(16) float g_s1[NPLANE];         // max of pass-1
__device__ __align__(16) float g_s2[NPLANE];         // max of pass-2

// ---------------------------------------------------------------------------
// conv1: y [4,2,224,224] -> g_y32 [4,32,224,224], 3x3 same
// ---------------------------------------------------------------------------
__global__ void __launch_bounds__(224) conv1_kernel(
    const float* __restrict__ y, const float* __restrict__ w3)
{
    int b = blockIdx.x / HH;
    int h = blockIdx.x % HH;
    int tid = threadIdx.x;

    __shared__ float si[2][3][WW + 2];
    __shared__ float sw[32 * 2 * 9];

    for (int i = tid; i < 576; i += 224) sw[i] = w3[i];

    #pragma unroll
    for (int ic = 0; ic < 2; ic++)
        #pragma unroll
        for (int r = 0; r < 3; r++) {
            int hh = h + r - 1;
            float v = (hh >= 0 && hh < HH)
                        ? y[((size_t)(b * 2 + ic) * HH + hh) * WW + tid] : 0.f;
            si[ic][r][tid + 1] = v;
            if (tid < 2) si[ic][r][tid * (WW + 1)] = 0.f;
        }
    __syncthreads();

    float v[18];
    #pragma unroll
    for (int ic = 0; ic < 2; ic++)
        #pragma unroll
        for (int r = 0; r < 3; r++)
            #pragma unroll
            for (int dx = 0; dx < 3; dx++)
                v[ic * 9 + r * 3 + dx] = si[ic][r][tid + dx];

    for (int oc = 0; oc < 32; oc++) {
        float acc = 0.f;
        #pragma unroll
        for (int k = 0; k < 18; k++) acc = fmaf(v[k], sw[oc * 18 + k], acc);
        g_y32[((size_t)(b * 32 + oc) * HH + h) * WW + tid] = acc;
    }
}

// ---------------------------------------------------------------------------
// Propagation (R1 structure; gates prenormalized in the load phase).
// One CTA per (dir, b, c) plane; 224 threads = vector dim.
// Scan step: LDS.128(nrm) + 2 hb LDS + 3 FMA + 2 STS, one barrier/step.
// dir map: 0=lr(hor,fwd) 1=rl(vert,rev) 2=du(vert,fwd) 3=ud(hor,rev)
// ---------------------------------------------------------------------------
__global__ void __launch_bounds__(224) prop_kernel(
    const float* __restrict__ gates, int pass)
{
    int pid = blockIdx.x;           // 0..511
    int d  = pid >> 7;
    int bc = pid & 127;
    int b  = bc >> 5;
    int c  = bc & 31;
    bool hor = (d == 0 || d == 3);
    bool rev = (d == 1 || d == 3);

    const float* xp  = (pass ? g_s1 : g_y32) + (size_t)bc * HW;
    float*       op  = g_dir + (size_t)(d * 128 + bc) * HW;
    const float* g1p = gates + ((size_t)b * GCH + d * 96 + c) * HW;
    const float* g2p = g1p + (size_t)32 * HW;
    const float* g3p = g1p + (size_t)64 * HW;

    __shared__ __align__(16) float nrm[224 * NSTR];  // (s1,s2,s3,base) per (el,step)
    __shared__ float to[WT * OSTR];
    __shared__ float hb[2][WW + 2];

    int tid = threadIdx.x;
    for (int i = tid; i < 2 * (WW + 2); i += 224) ((float*)hb)[i] = 0.f;

    float hreg = 0.f;

    for (int tb = 0; tb < HH / WT; tb++) {
        int t0 = tb * WT;

        // ---- load + normalize (off the barrier-paced path) ----
        if (hor) {
            #pragma unroll
            for (int i = 0; i < WT; i++) {
                int idx = i * 224 + tid;
                int s = idx >> 3, j = idx & 7;
                int tg = rev ? (223 - t0 - j) : (t0 + j);
                int off = s * WW + tg;
                float a1 = g1p[off], a2 = g2p[off], a3 = g3p[off], xv = xp[off];
                float inv = __fdividef(1.0f,
                    fmaxf(fabsf(a1) + fabsf(a2) + fabsf(a3), 1.0f));
                *(float4*)&nrm[s * NSTR + 4 * j] =
                    make_float4(a1 * inv, a2 * inv, a3 * inv,
                                (1.0f - (a1 + a2 + a3) * inv) * xv);
            }
        } else {
            #pragma unroll
            for (int i = 0; i < WT; i++) {
                int tg = rev ? (223 - t0 - i) : (t0 + i);
                int off = tg * WW + tid;
                float a1 = g1p[off], a2 = g2p[off], a3 = g3p[off], xv = xp[off];
                float inv = __fdividef(1.0f,
                    fmaxf(fabsf(a1) + fabsf(a2) + fabsf(a3), 1.0f));
                *(float4*)&nrm[tid * NSTR + 4 * i] =
                    make_float4(a1 * inv, a2 * inv, a3 * inv,
                                (1.0f - (a1 + a2 + a3) * inv) * xv);
            }
        }
        __syncthreads();

        // ---- serial scan over WT steps (lean, barrier-paced) ----
        #pragma unroll
        for (int j = 0; j < WT; j++) {
            int t = t0 + j;
            const float* hp = hb[t & 1];
            float*       hc = hb[(t & 1) ^ 1];
            float4 q = *(const float4*)&nrm[tid * NSTR + 4 * j];
            float hn = fmaf(q.x, hp[tid],
                       fmaf(q.y, hreg,
                       fmaf(q.z, hp[tid + 2], q.w)));
            hc[tid + 1] = hn;
            to[j * OSTR + tid] = hn;
            hreg = hn;
            __syncthreads();
        }

        // ---- flush output tile (coalesced stores) ----
        if (hor) {
            #pragma unroll
            for (int i = 0; i < WT; i++) {
                int idx = i * 224 + tid;
                int s = idx >> 3, j = idx & 7;
                int tg = rev ? (223 - t0 - j) : (t0 + j);
                op[s * WW + tg] = to[j * OSTR + s];
            }
        } else {
            #pragma unroll
            for (int i = 0; i < WT; i++) {
                int tg = rev ? (223 - t0 - i) : (t0 + i);
                op[tg * WW + tid] = to[i * OSTR + tid];
            }
        }
        // next tile's load-sync orders flush reads before buffers are rewritten
    }
}

// ---------------------------------------------------------------------------
// max over 4 direction buffers -> g_s1 (pass 0) or g_s2 (pass 1)
// ---------------------------------------------------------------------------
__global__ void max_kernel(int pass)
{
    int i = blockIdx.x * blockDim.x + threadIdx.x;
    if (i >= N4) return;
    const float4* d0 = (const float4*)g_dir;
    float4 a = d0[i];
    float4 b = d0[i + N4];
    float4 c = d0[i + 2 * N4];
    float4 e = d0[i + 3 * N4];
    float4 r;
    r.x = fmaxf(fmaxf(a.x, b.x), fmaxf(c.x, e.x));
    r.y = fmaxf(fmaxf(a.y, b.y), fmaxf(c.y, e.y));
    r.z = fmaxf(fmaxf(a.z, b.z), fmaxf(c.z, e.z));
    r.w = fmaxf(fmaxf(a.w, b.w), fmaxf(c.w, e.w));
    float4* dst = (float4*)(pass ? g_s2 : g_s1);
    dst[i] = r;
}

// ---------------------------------------------------------------------------
// conv2 (32->2, 3x3 same) + log_softmax over channel dim (2)
// ---------------------------------------------------------------------------
__global__ void __launch_bounds__(224) conv2_ls_kernel(
    const float* __restrict__ w4, float* __restrict__ out)
{
    int b = blockIdx.x / HH;
    int h = blockIdx.x % HH;
    int tid = threadIdx.x;

    __shared__ float si[16][3][WW + 2];
    __shared__ float sw[2 * 32 * 9];

    for (int i = tid; i < 576; i += 224) sw[i] = w4[i];

    float acc0 = 0.f, acc1 = 0.f;

    for (int chunk = 0; chunk < 2; chunk++) {
        __syncthreads();
        for (int icl = 0; icl < 16; icl++) {
            int ic = chunk * 16 + icl;
            #pragma unroll
            for (int r = 0; r < 3; r++) {
                int hh = h + r - 1;
                float v = (hh >= 0 && hh < HH)
                    ? g_s2[((size_t)(b * 32 + ic) * HH + hh) * WW + tid] : 0.f;
                si[icl][r][tid + 1] = v;
                if (tid < 2) si[icl][r][tid * (WW + 1)] = 0.f;
            }
        }
        __syncthreads();
        for (int icl = 0; icl < 16; icl++) {
            int ic = chunk * 16 + icl;
            #pragma unroll
            for (int r = 0; r < 3; r++)
                #pragma unroll
                for (int dx = 0; dx < 3; dx++) {
                    float v = si[icl][r][tid + dx];
                    int k = ic * 9 + r * 3 + dx;
                    acc0 = fmaf(v, sw[k], acc0);
                    acc1 = fmaf(v, sw[288 + k], acc1);
                }
        }
    }

    float m  = fmaxf(acc0, acc1);
    float e0 = __expf(acc0 - m), e1 = __expf(acc1 - m);
    float lse = m + __logf(e0 + e1);
    size_t o = ((size_t)b * 2 * HH + h) * WW + tid;
    out[o]      = acc0 - lse;
    out[o + HW] = acc1 - lse;
}

// ---------------------------------------------------------------------------
extern "C" void kernel_launch(void* const* d_in, const int* in_sizes, int n_in,
                              void* d_out, int out_size)
{
    const float* gates = (const float*)d_in[0];  // [4,384,224,224]
    const float* y     = (const float*)d_in[1];  // [4,2,224,224]
    const float* w3    = (const float*)d_in[2];  // [32,2,3,3]
    const float* w4    = (const float*)d_in[3];  // [2,32,3,3]
    float* out = (float*)d_out;                  // [4,2,224,224]

    (void)in_sizes; (void)n_in; (void)out_size;

    conv1_kernel<<<BB * HH, 224>>>(y, w3);
    prop_kernel<<<512, 224>>>(gates, 0);      // g_y32 -> g_dir
    max_kernel<<<(N4 + 255) / 256, 256>>>(0); // g_dir -> g_s1
    prop_kernel<<<512, 224>>>(gates, 1);      // g_s1 -> g_dir
    max_kernel<<<(N4 + 255) / 256, 256>>>(1); // g_dir -> g_s2
    conv2_ls_kernel<<<BB * HH, 224>>>(w4, out);
}